// round 1
// baseline (speedup 1.0000x reference)
#include <cuda_runtime.h>
#include <math.h>

// Problem constants
#define BATCH 16
#define SEQ   2048
#define EMB   1024
#define MTOT  (BATCH * SEQ)          // 32768

// Scratch in __device__ globals (no allocation allowed)
__device__ float g_q[(size_t)BATCH * SEQ * EMB];
__device__ float g_k[(size_t)BATCH * SEQ * EMB];
__device__ float g_v[(size_t)BATCH * SEQ * EMB];
__device__ float g_s[(size_t)BATCH * SEQ * SEQ];

// ---------------------------------------------------------------------------
// Tiled SGEMM: C[m,n] = alpha * sum_k A[m,k] * B(k,n)  (+ bias[n])
//   BT = true :  B stored [N,K] row-major (use B[n*K+k])   -> NT gemm
//   BT = false:  B stored [K,N] row-major (use B[k*N+n])   -> NN gemm
// BM=BN=128, BK=8, 256 threads, 8x8 per-thread tile. All dims divide evenly.
// ---------------------------------------------------------------------------
#define BM 128
#define BN 128
#define BK 8
#define TM 8
#define TN 8

template <bool BT>
__global__ __launch_bounds__(256)
void sgemm_kernel(const float* __restrict__ A,
                  const float* __restrict__ B,
                  const float* __restrict__ bias,
                  float* __restrict__ C,
                  int M, int N, int K, float alpha,
                  long long a_bstride, long long b_bstride, long long c_bstride)
{
    __shared__ float As[BK][BM];
    __shared__ float Bs[BK][BN];

    const long long bz = blockIdx.z;
    A += bz * a_bstride;
    B += bz * b_bstride;
    C += bz * c_bstride;

    const int bm = blockIdx.y * BM;
    const int bn = blockIdx.x * BN;
    const int tid = threadIdx.x;

    const int tx = tid & 15;   // N direction (16 threads)
    const int ty = tid >> 4;   // M direction (16 threads)

    float acc[TM][TN];
#pragma unroll
    for (int i = 0; i < TM; i++)
#pragma unroll
        for (int j = 0; j < TN; j++) acc[i][j] = 0.0f;

    // A-tile loader indices (also B-tile loader when BT)
    const int arow = tid >> 1;          // 0..127
    const int acol = (tid & 1) * 4;     // 0 or 4
    // B-tile loader indices when !BT
    const int brow = tid >> 5;          // 0..7 (k)
    const int bcol = (tid & 31) * 4;    // 0..124 (n)

    for (int k0 = 0; k0 < K; k0 += BK) {
        // Load A tile [BM x BK], store transposed into As[k][m]
        float4 a4 = *reinterpret_cast<const float4*>(
            A + (long long)(bm + arow) * K + k0 + acol);
        As[acol + 0][arow] = a4.x;
        As[acol + 1][arow] = a4.y;
        As[acol + 2][arow] = a4.z;
        As[acol + 3][arow] = a4.w;

        if (BT) {
            // B is [N,K]: tile [BN x BK], store transposed into Bs[k][n]
            float4 b4 = *reinterpret_cast<const float4*>(
                B + (long long)(bn + arow) * K + k0 + acol);
            Bs[acol + 0][arow] = b4.x;
            Bs[acol + 1][arow] = b4.y;
            Bs[acol + 2][arow] = b4.z;
            Bs[acol + 3][arow] = b4.w;
        } else {
            // B is [K,N]: tile [BK x BN], direct store
            float4 b4 = *reinterpret_cast<const float4*>(
                B + (long long)(k0 + brow) * N + bn + bcol);
            *reinterpret_cast<float4*>(&Bs[brow][bcol]) = b4;
        }
        __syncthreads();

#pragma unroll
        for (int kk = 0; kk < BK; kk++) {
            float areg[TM], breg[TN];
#pragma unroll
            for (int i = 0; i < TM; i++) areg[i] = As[kk][ty * TM + i];
#pragma unroll
            for (int j = 0; j < TN; j++) breg[j] = Bs[kk][tx * TN + j];
#pragma unroll
            for (int i = 0; i < TM; i++)
#pragma unroll
                for (int j = 0; j < TN; j++)
                    acc[i][j] = fmaf(areg[i], breg[j], acc[i][j]);
        }
        __syncthreads();
    }

    // Epilogue
#pragma unroll
    for (int i = 0; i < TM; i++) {
        const long long m = bm + ty * TM + i;
#pragma unroll
        for (int j = 0; j < TN; j += 4) {
            const int n = bn + tx * TN + j;
            float4 o;
            o.x = alpha * acc[i][j + 0];
            o.y = alpha * acc[i][j + 1];
            o.z = alpha * acc[i][j + 2];
            o.w = alpha * acc[i][j + 3];
            if (bias != nullptr) {
                o.x += bias[n + 0];
                o.y += bias[n + 1];
                o.z += bias[n + 2];
                o.w += bias[n + 3];
            }
            *reinterpret_cast<float4*>(C + m * N + n) = o;
        }
    }
}

// ---------------------------------------------------------------------------
// Row softmax over rows of length SEQ (2048). One block (256 thr) per row.
// Each thread caches its 8 elements in registers: single global read+write.
// ---------------------------------------------------------------------------
__global__ __launch_bounds__(256)
void softmax_kernel(float* __restrict__ s)
{
    float* row = s + (long long)blockIdx.x * SEQ;
    const int tid = threadIdx.x;
    __shared__ float red[256];

    float r[8];
    float m = -3.402823466e+38f;
#pragma unroll
    for (int i = 0; i < 8; i++) {
        r[i] = row[tid + i * 256];
        m = fmaxf(m, r[i]);
    }
    red[tid] = m;
    __syncthreads();
#pragma unroll
    for (int stp = 128; stp > 0; stp >>= 1) {
        if (tid < stp) red[tid] = fmaxf(red[tid], red[tid + stp]);
        __syncthreads();
    }
    m = red[0];
    __syncthreads();

    float sum = 0.0f;
#pragma unroll
    for (int i = 0; i < 8; i++) {
        r[i] = __expf(r[i] - m);
        sum += r[i];
    }
    red[tid] = sum;
    __syncthreads();
#pragma unroll
    for (int stp = 128; stp > 0; stp >>= 1) {
        if (tid < stp) red[tid] += red[tid + stp];
        __syncthreads();
    }
    const float inv = 1.0f / red[0];
    __syncthreads();

#pragma unroll
    for (int i = 0; i < 8; i++)
        row[tid + i * 256] = r[i] * inv;
}

// ---------------------------------------------------------------------------
// kernel_launch
// ---------------------------------------------------------------------------
extern "C" void kernel_launch(void* const* d_in, const int* in_sizes, int n_in,
                              void* d_out, int out_size)
{
    const float* x  = (const float*)d_in[0];
    const float* Wq = (const float*)d_in[1];
    const float* bq = (const float*)d_in[2];
    const float* Wk = (const float*)d_in[3];
    const float* bk = (const float*)d_in[4];
    const float* Wv = (const float*)d_in[5];
    const float* bv = (const float*)d_in[6];
    float* out = (float*)d_out;

    float *q, *k, *v, *s;
    cudaGetSymbolAddress((void**)&q, g_q);
    cudaGetSymbolAddress((void**)&k, g_k);
    cudaGetSymbolAddress((void**)&v, g_v);
    cudaGetSymbolAddress((void**)&s, g_s);

    const float scale = 1.0f / sqrtf((float)EMB);

    // 1) QKV projections: C[M=32768, N=1024] = x @ W^T + b  (NT)
    {
        dim3 grid(EMB / BN, MTOT / BM, 1);
        sgemm_kernel<true><<<grid, 256>>>(x, Wq, bq, q, MTOT, EMB, EMB, 1.0f, 0, 0, 0);
        sgemm_kernel<true><<<grid, 256>>>(x, Wk, bk, k, MTOT, EMB, EMB, 1.0f, 0, 0, 0);
        sgemm_kernel<true><<<grid, 256>>>(x, Wv, bv, v, MTOT, EMB, EMB, 1.0f, 0, 0, 0);
    }

    // 2) Scores: per batch, S[s,t] = scale * q[s,:] . k[t,:]   (NT, batched)
    {
        dim3 grid(SEQ / BN, SEQ / BM, BATCH);
        sgemm_kernel<true><<<grid, 256>>>(
            q, k, nullptr, s, SEQ, SEQ, EMB, scale,
            (long long)SEQ * EMB, (long long)SEQ * EMB, (long long)SEQ * SEQ);
    }

    // 3) Softmax over last dim
    softmax_kernel<<<BATCH * SEQ, 256>>>(s);

    // 4) Output: per batch, O[s,d] = P[s,:] @ v[:,d]   (NN, batched)
    {
        dim3 grid(EMB / BN, SEQ / BM, BATCH);
        sgemm_kernel<false><<<grid, 256>>>(
            s, v, nullptr, out, SEQ, EMB, SEQ, 1.0f,
            (long long)SEQ * SEQ, (long long)SEQ * EMB, (long long)SEQ * EMB);
    }
}

// round 3
// speedup vs baseline: 2.2806x; 2.2806x over previous
#include <cuda_runtime.h>
#include <cuda_bf16.h>
#include <cstdint>
#include <math.h>

// ---------------------------------------------------------------------------
// Problem constants
// ---------------------------------------------------------------------------
#define BATCH 16
#define SEQ   2048
#define EMB   1024
#define MTOT  (BATCH * SEQ)          // 32768

// ---------------------------------------------------------------------------
// Scratch (__device__ globals; no allocation allowed)
// ---------------------------------------------------------------------------
__device__ float g_q[(size_t)MTOT * EMB];
__device__ float g_k[(size_t)MTOT * EMB];
__device__ float g_v[(size_t)MTOT * EMB];
__device__ float g_vt[(size_t)MTOT * EMB];            // [B][E][S]
__device__ float g_s[(size_t)BATCH * SEQ * SEQ];

// ---------------------------------------------------------------------------
// MMA helpers (plain sm_80+ ISA: works under compute_103 target)
// ---------------------------------------------------------------------------
__device__ __forceinline__ uint32_t smem_u32(const void* p) {
    uint32_t a;
    asm("{ .reg .u64 t; cvta.to.shared.u64 t, %1; cvt.u32.u64 %0, t; }"
        : "=r"(a) : "l"(p));
    return a;
}

#define LDSM_X4(r0, r1, r2, r3, addr)                                        \
    asm volatile("ldmatrix.sync.aligned.m8n8.x4.shared.b16 "                 \
                 "{%0,%1,%2,%3}, [%4];"                                      \
                 : "=r"(r0), "=r"(r1), "=r"(r2), "=r"(r3) : "r"(addr))

#define MMA16816(d, a, b0, b1)                                               \
    asm volatile("mma.sync.aligned.m16n8k16.row.col.f32.bf16.bf16.f32 "      \
                 "{%0,%1,%2,%3},{%4,%5,%6,%7},{%8,%9},{%0,%1,%2,%3};"        \
                 : "+f"((d)[0]), "+f"((d)[1]), "+f"((d)[2]), "+f"((d)[3])    \
                 : "r"((a)[0]), "r"((a)[1]), "r"((a)[2]), "r"((a)[3]),       \
                   "r"(b0), "r"(b1))

__device__ __forceinline__ uint32_t pack_hi2(float x, float y) {
    __nv_bfloat162 t = __floats2bfloat162_rn(x, y);
    return *reinterpret_cast<uint32_t*>(&t);
}
__device__ __forceinline__ uint32_t pack_lo2(float x, float y) {
    float hx = __bfloat162float(__float2bfloat16_rn(x));
    float hy = __bfloat162float(__float2bfloat16_rn(y));
    __nv_bfloat162 t = __floats2bfloat162_rn(x - hx, y - hy);
    return *reinterpret_cast<uint32_t*>(&t);
}

// ---------------------------------------------------------------------------
// Split-bf16 NT GEMM on tensor cores (mma.sync):
//   C[m,n] = alpha * sum_k A[m,k] * B[n,k]  (+ bias[n])
// A,B fp32 in global; converted to bf16 (hi,lo) while staging to SMEM.
// 3-term emulation: AhBh + AhBl + AlBh, fp32 accumulation.
// CTA tile 128x128x32, 8 warps (4m x 2n), double-buffered SMEM.
// ---------------------------------------------------------------------------
#define BM 128
#define BN 128
#define BK 32
#define PLANE 8192                        // 128 rows x 64 B (BK bf16)
#define STAGE_BYTES (4 * PLANE)           // Ah, Al, Bh, Bl
#define GSMEM (2 * STAGE_BYTES)           // 64 KB

__global__ void __launch_bounds__(256, 1)
gemm_mma_kernel(const float* __restrict__ A,
                const float* __restrict__ B,
                const float* __restrict__ bias,
                float* __restrict__ C,
                int K, int lda, int ldb, int ldc, float alpha,
                long long a_bs, long long b_bs, long long c_bs)
{
    extern __shared__ char smem[];
    const uint32_t sbase = smem_u32(smem);

    const int tid  = threadIdx.x;
    const int wid  = tid >> 5;
    const int lane = tid & 31;

    const long long bz = blockIdx.z;
    A += bz * a_bs;
    B += bz * b_bs;
    C += bz * c_bs;

    const int tile_m = blockIdx.y * BM;
    const int tile_n = blockIdx.x * BN;

    // warp tile: 4 warps in m (32 rows each), 2 in n (64 cols each)
    const int wm = wid & 3;
    const int wn = wid >> 2;

    // Loader mapping: thread -> (row, half). row 0..127, half 0/1 (16 fp32).
    const int lrow  = tid >> 1;
    const int lhalf = tid & 1;
    const float* gA = A + (long long)(tile_m + lrow) * lda + lhalf * 16;
    const float* gB = B + (long long)(tile_n + lrow) * ldb + lhalf * 16;
    const uint32_t swz   = (lrow >> 1) & 3;
    const uint32_t sts_o0 = lrow * 64 + (((lhalf * 2 + 0) ^ swz) << 4);
    const uint32_t sts_o1 = lrow * 64 + (((lhalf * 2 + 1) ^ swz) << 4);

    float acc[2][8][4];
#pragma unroll
    for (int i = 0; i < 2; i++)
#pragma unroll
        for (int j = 0; j < 8; j++)
#pragma unroll
            for (int t = 0; t < 4; t++) acc[i][j][t] = 0.0f;

    float4 ra[4], rb[4];
    // Preload chunk 0
#pragma unroll
    for (int i = 0; i < 4; i++) {
        ra[i] = *reinterpret_cast<const float4*>(gA + i * 4);
        rb[i] = *reinterpret_cast<const float4*>(gB + i * 4);
    }

    const int nchunks = K / BK;
    for (int c = 0; c < nchunks; c++) {
        const uint32_t st = sbase + (c & 1) * STAGE_BYTES;

        // Stage current chunk: convert fp32 -> bf16 hi/lo, swizzled STS
        {
            uint4 h0, h1, l0, l1;
            h0.x = pack_hi2(ra[0].x, ra[0].y); h0.y = pack_hi2(ra[0].z, ra[0].w);
            h0.z = pack_hi2(ra[1].x, ra[1].y); h0.w = pack_hi2(ra[1].z, ra[1].w);
            h1.x = pack_hi2(ra[2].x, ra[2].y); h1.y = pack_hi2(ra[2].z, ra[2].w);
            h1.z = pack_hi2(ra[3].x, ra[3].y); h1.w = pack_hi2(ra[3].z, ra[3].w);
            l0.x = pack_lo2(ra[0].x, ra[0].y); l0.y = pack_lo2(ra[0].z, ra[0].w);
            l0.z = pack_lo2(ra[1].x, ra[1].y); l0.w = pack_lo2(ra[1].z, ra[1].w);
            l1.x = pack_lo2(ra[2].x, ra[2].y); l1.y = pack_lo2(ra[2].z, ra[2].w);
            l1.z = pack_lo2(ra[3].x, ra[3].y); l1.w = pack_lo2(ra[3].z, ra[3].w);
            *reinterpret_cast<uint4*>(smem + (st - sbase) + sts_o0)          = h0;
            *reinterpret_cast<uint4*>(smem + (st - sbase) + sts_o1)          = h1;
            *reinterpret_cast<uint4*>(smem + (st - sbase) + PLANE + sts_o0)  = l0;
            *reinterpret_cast<uint4*>(smem + (st - sbase) + PLANE + sts_o1)  = l1;

            h0.x = pack_hi2(rb[0].x, rb[0].y); h0.y = pack_hi2(rb[0].z, rb[0].w);
            h0.z = pack_hi2(rb[1].x, rb[1].y); h0.w = pack_hi2(rb[1].z, rb[1].w);
            h1.x = pack_hi2(rb[2].x, rb[2].y); h1.y = pack_hi2(rb[2].z, rb[2].w);
            h1.z = pack_hi2(rb[3].x, rb[3].y); h1.w = pack_hi2(rb[3].z, rb[3].w);
            l0.x = pack_lo2(rb[0].x, rb[0].y); l0.y = pack_lo2(rb[0].z, rb[0].w);
            l0.z = pack_lo2(rb[1].x, rb[1].y); l0.w = pack_lo2(rb[1].z, rb[1].w);
            l1.x = pack_lo2(rb[2].x, rb[2].y); l1.y = pack_lo2(rb[2].z, rb[2].w);
            l1.z = pack_lo2(rb[3].x, rb[3].y); l1.w = pack_lo2(rb[3].z, rb[3].w);
            *reinterpret_cast<uint4*>(smem + (st - sbase) + 2 * PLANE + sts_o0) = h0;
            *reinterpret_cast<uint4*>(smem + (st - sbase) + 2 * PLANE + sts_o1) = h1;
            *reinterpret_cast<uint4*>(smem + (st - sbase) + 3 * PLANE + sts_o0) = l0;
            *reinterpret_cast<uint4*>(smem + (st - sbase) + 3 * PLANE + sts_o1) = l1;
        }
        __syncthreads();

        // Prefetch next chunk while computing this one
        if (c + 1 < nchunks) {
            const float* pA = gA + (long long)(c + 1) * BK;
            const float* pB = gB + (long long)(c + 1) * BK;
#pragma unroll
            for (int i = 0; i < 4; i++) {
                ra[i] = *reinterpret_cast<const float4*>(pA + i * 4);
                rb[i] = *reinterpret_cast<const float4*>(pB + i * 4);
            }
        }

        // MMA over the staged chunk
        const uint32_t sAh = st;
        const uint32_t sAl = st + PLANE;
        const uint32_t sBh = st + 2 * PLANE;
        const uint32_t sBl = st + 3 * PLANE;
        const int lr = lane & 15;           // ldmatrix row within 16
        const int lg = lane >> 4;           // k granule 0/1

#pragma unroll
        for (int ks = 0; ks < 2; ks++) {
            const uint32_t g = ks * 2 + lg;

            uint32_t ah[2][4], al[2][4];
#pragma unroll
            for (int mt = 0; mt < 2; mt++) {
                const int row = wm * 32 + mt * 16 + lr;
                const uint32_t off = row * 64 + (((g) ^ ((row >> 1) & 3)) << 4);
                LDSM_X4(ah[mt][0], ah[mt][1], ah[mt][2], ah[mt][3], sAh + off);
                LDSM_X4(al[mt][0], al[mt][1], al[mt][2], al[mt][3], sAl + off);
            }
            uint32_t bh[4][4], bl[4][4];
#pragma unroll
            for (int bt = 0; bt < 4; bt++) {
                const int row = wn * 64 + bt * 16 + lr;
                const uint32_t off = row * 64 + (((g) ^ ((row >> 1) & 3)) << 4);
                LDSM_X4(bh[bt][0], bh[bt][1], bh[bt][2], bh[bt][3], sBh + off);
                LDSM_X4(bl[bt][0], bl[bt][1], bl[bt][2], bl[bt][3], sBl + off);
            }
#pragma unroll
            for (int mt = 0; mt < 2; mt++) {
#pragma unroll
                for (int bt = 0; bt < 4; bt++) {
                    // n-tile 2*bt   : B regs {0, 2}
                    MMA16816(acc[mt][bt * 2 + 0], ah[mt], bh[bt][0], bh[bt][2]);
                    MMA16816(acc[mt][bt * 2 + 0], ah[mt], bl[bt][0], bl[bt][2]);
                    MMA16816(acc[mt][bt * 2 + 0], al[mt], bh[bt][0], bh[bt][2]);
                    // n-tile 2*bt+1 : B regs {1, 3}
                    MMA16816(acc[mt][bt * 2 + 1], ah[mt], bh[bt][1], bh[bt][3]);
                    MMA16816(acc[mt][bt * 2 + 1], ah[mt], bl[bt][1], bl[bt][3]);
                    MMA16816(acc[mt][bt * 2 + 1], al[mt], bh[bt][1], bh[bt][3]);
                }
            }
        }
        __syncthreads();
    }

    // Epilogue: frag layout m16n8 -> thread (lane>>2, (lane&3)*2), rows +8
    const int er = lane >> 2;
    const int ec = (lane & 3) * 2;
#pragma unroll
    for (int mt = 0; mt < 2; mt++) {
#pragma unroll
        for (int half = 0; half < 2; half++) {
            const long long grow = tile_m + wm * 32 + mt * 16 + half * 8 + er;
#pragma unroll
            for (int nt = 0; nt < 8; nt++) {
                const int gcol = tile_n + wn * 64 + nt * 8 + ec;
                float2 o;
                o.x = alpha * acc[mt][nt][half * 2 + 0];
                o.y = alpha * acc[mt][nt][half * 2 + 1];
                if (bias != nullptr) {
                    o.x += __ldg(bias + gcol + 0);
                    o.y += __ldg(bias + gcol + 1);
                }
                *reinterpret_cast<float2*>(C + grow * ldc + gcol) = o;
            }
        }
    }
}

// ---------------------------------------------------------------------------
// v [B][S][E] -> vT [B][E][S]  (fp32, 32x32 smem tiles)
// ---------------------------------------------------------------------------
__global__ void __launch_bounds__(1024)
transpose_kernel(const float* __restrict__ v, float* __restrict__ vt)
{
    __shared__ float tile[32][33];
    const int b  = blockIdx.z;
    const int d0 = blockIdx.x * 32;
    const int t0 = blockIdx.y * 32;
    const int tx = threadIdx.x;
    const int ty = threadIdx.y;

    tile[ty][tx] = v[((long long)b * SEQ + t0 + ty) * EMB + d0 + tx];
    __syncthreads();
    vt[((long long)b * EMB + d0 + ty) * SEQ + t0 + tx] = tile[tx][ty];
}

// ---------------------------------------------------------------------------
// Row softmax over rows of length SEQ (2048). One 256-thread block per row.
// ---------------------------------------------------------------------------
__global__ void __launch_bounds__(256)
softmax_kernel(float* __restrict__ s)
{
    float* row = s + (long long)blockIdx.x * SEQ;
    const int tid = threadIdx.x;
    __shared__ float red[256];

    float r[8];
    float m = -3.402823466e+38f;
#pragma unroll
    for (int i = 0; i < 8; i++) {
        r[i] = row[tid + i * 256];
        m = fmaxf(m, r[i]);
    }
    red[tid] = m;
    __syncthreads();
#pragma unroll
    for (int stp = 128; stp > 0; stp >>= 1) {
        if (tid < stp) red[tid] = fmaxf(red[tid], red[tid + stp]);
        __syncthreads();
    }
    m = red[0];
    __syncthreads();

    float sum = 0.0f;
#pragma unroll
    for (int i = 0; i < 8; i++) {
        r[i] = __expf(r[i] - m);
        sum += r[i];
    }
    red[tid] = sum;
    __syncthreads();
#pragma unroll
    for (int stp = 128; stp > 0; stp >>= 1) {
        if (tid < stp) red[tid] += red[tid + stp];
        __syncthreads();
    }
    const float inv = 1.0f / red[0];
    __syncthreads();

#pragma unroll
    for (int i = 0; i < 8; i++)
        row[tid + i * 256] = r[i] * inv;
}

// ---------------------------------------------------------------------------
// kernel_launch
// ---------------------------------------------------------------------------
extern "C" void kernel_launch(void* const* d_in, const int* in_sizes, int n_in,
                              void* d_out, int out_size)
{
    const float* x  = (const float*)d_in[0];
    const float* Wq = (const float*)d_in[1];
    const float* bq = (const float*)d_in[2];
    const float* Wk = (const float*)d_in[3];
    const float* bk = (const float*)d_in[4];
    const float* Wv = (const float*)d_in[5];
    const float* bv = (const float*)d_in[6];
    float* out = (float*)d_out;

    float *q, *k, *v, *vt, *s;
    cudaGetSymbolAddress((void**)&q,  g_q);
    cudaGetSymbolAddress((void**)&k,  g_k);
    cudaGetSymbolAddress((void**)&v,  g_v);
    cudaGetSymbolAddress((void**)&vt, g_vt);
    cudaGetSymbolAddress((void**)&s,  g_s);

    cudaFuncSetAttribute(gemm_mma_kernel,
                         cudaFuncAttributeMaxDynamicSharedMemorySize, GSMEM);

    const float scale = 1.0f / sqrtf((float)EMB);
    const long long SE = (long long)SEQ * EMB;     // 2M
    const long long SS = (long long)SEQ * SEQ;     // 4M

    // 1) QKV projections: [32768,1024] = x @ W^T + b   (NT)
    {
        dim3 grid(EMB / BN, MTOT / BM, 1);
        gemm_mma_kernel<<<grid, 256, GSMEM>>>(x, Wq, bq, q, EMB, EMB, EMB, EMB, 1.0f, 0, 0, 0);
        gemm_mma_kernel<<<grid, 256, GSMEM>>>(x, Wk, bk, k, EMB, EMB, EMB, EMB, 1.0f, 0, 0, 0);
        gemm_mma_kernel<<<grid, 256, GSMEM>>>(x, Wv, bv, v, EMB, EMB, EMB, EMB, 1.0f, 0, 0, 0);
    }

    // 2) Transpose v -> vT [B][E][S]
    {
        dim3 grid(EMB / 32, SEQ / 32, BATCH);
        transpose_kernel<<<grid, dim3(32, 32, 1)>>>(v, vt);
    }

    // 3) Scores: per batch, S = scale * q @ k^T   (NT, batched)
    {
        dim3 grid(SEQ / BN, SEQ / BM, BATCH);
        gemm_mma_kernel<<<grid, 256, GSMEM>>>(q, k, nullptr, s, EMB, EMB, EMB, SEQ,
                                              scale, SE, SE, SS);
    }

    // 4) Softmax
    softmax_kernel<<<BATCH * SEQ, 256>>>(s);

    // 5) Output: per batch, O[s,d] = sum_t P[s,t] * vT[d,t]   (NT, batched)
    {
        dim3 grid(EMB / BN, SEQ / BM, BATCH);
        gemm_mma_kernel<<<grid, 256, GSMEM>>>(s, vt, nullptr, out, SEQ, SEQ, SEQ, EMB,
                                              1.0f, SS, SE, SE);
    }
}

// round 4
// speedup vs baseline: 3.7118x; 1.6275x over previous
#include <cuda_runtime.h>
#include <cuda_fp16.h>
#include <cstdint>
#include <math.h>

// ---------------------------------------------------------------------------
// Problem constants
// ---------------------------------------------------------------------------
#define BATCH 16
#define SEQ   2048
#define EMB   1024
#define MTOT  (BATCH * SEQ)          // 32768

// ---------------------------------------------------------------------------
// Scratch (__device__ globals; no allocation allowed)
// ---------------------------------------------------------------------------
__device__ __half g_q[(size_t)MTOT * EMB];
__device__ __half g_k[(size_t)MTOT * EMB];
__device__ __half g_v[(size_t)MTOT * EMB];
__device__ __half g_vt[(size_t)MTOT * EMB];           // [B][E][S]
__device__ float  g_s[(size_t)BATCH * SEQ * SEQ];
__device__ __half g_p[(size_t)BATCH * SEQ * SEQ];

// ---------------------------------------------------------------------------
// MMA helpers (plain sm_80+ ISA: compiles under compute_103 target)
// ---------------------------------------------------------------------------
__device__ __forceinline__ uint32_t smem_u32(const void* p) {
    uint32_t a;
    asm("{ .reg .u64 t; cvta.to.shared.u64 t, %1; cvt.u32.u64 %0, t; }"
        : "=r"(a) : "l"(p));
    return a;
}

#define LDSM_X4(r0, r1, r2, r3, addr)                                        \
    asm volatile("ldmatrix.sync.aligned.m8n8.x4.shared.b16 "                 \
                 "{%0,%1,%2,%3}, [%4];"                                      \
                 : "=r"(r0), "=r"(r1), "=r"(r2), "=r"(r3) : "r"(addr))

#define MMA16816F16(d, a, b0, b1)                                            \
    asm volatile("mma.sync.aligned.m16n8k16.row.col.f32.f16.f16.f32 "        \
                 "{%0,%1,%2,%3},{%4,%5,%6,%7},{%8,%9},{%0,%1,%2,%3};"        \
                 : "+f"((d)[0]), "+f"((d)[1]), "+f"((d)[2]), "+f"((d)[3])    \
                 : "r"((a)[0]), "r"((a)[1]), "r"((a)[2]), "r"((a)[3]),       \
                   "r"(b0), "r"(b1))

__device__ __forceinline__ uint32_t pack_h2(float x, float y) {
    __half2 t = __floats2half2_rn(x, y);
    return *reinterpret_cast<uint32_t*>(&t);
}

// ---------------------------------------------------------------------------
// fp16 NT GEMM on tensor cores (mma.sync, fp32 accumulate):
//   C[m,n] = alpha * sum_k A[m,k] * B[n,k]  (+ bias[n])
// IN16:  A,B are __half in global (direct staging).
// !IN16: A,B are float in global; converted to fp16 while staging to SMEM.
// OUT16: C written as __half; else float.
// CTA tile 128x128x32, 8 warps (4m x 2n), double-buffered swizzled SMEM.
// ---------------------------------------------------------------------------
#define BM 128
#define BN 128
#define BK 32
#define PLANE 8192                        // 128 rows x 64 B (BK fp16)
#define STAGE_BYTES (2 * PLANE)           // A, B
#define GSMEM (2 * STAGE_BYTES)           // 32 KB

template <bool IN16, bool OUT16>
__global__ void __launch_bounds__(256, 1)
gemm_h_kernel(const void* __restrict__ Av,
              const void* __restrict__ Bv,
              const float* __restrict__ bias,
              void* __restrict__ Cv,
              int K, int lda, int ldb, int ldc, float alpha,
              long long a_bs, long long b_bs, long long c_bs)
{
    extern __shared__ char smem[];
    const uint32_t sbase = smem_u32(smem);

    const int tid  = threadIdx.x;
    const int wid  = tid >> 5;
    const int lane = tid & 31;

    const long long bz = blockIdx.z;
    const int tile_m = blockIdx.y * BM;
    const int tile_n = blockIdx.x * BN;

    // warp tile: 4 warps in m (32 rows each), 2 in n (64 cols each)
    const int wm = wid & 3;
    const int wn = wid >> 2;

    // Loader mapping: thread -> (row 0..127, half 0/1 of 16 elements)
    const int lrow  = tid >> 1;
    const int lhalf = tid & 1;
    const uint32_t swz    = (lrow >> 1) & 3;
    const uint32_t sts_o0 = lrow * 64 + (((lhalf * 2 + 0) ^ swz) << 4);
    const uint32_t sts_o1 = lrow * 64 + (((lhalf * 2 + 1) ^ swz) << 4);

    const float*  gAf = nullptr; const float*  gBf = nullptr;
    const __half* gAh = nullptr; const __half* gBh = nullptr;
    if (IN16) {
        gAh = (const __half*)Av + bz * a_bs + (long long)(tile_m + lrow) * lda + lhalf * 16;
        gBh = (const __half*)Bv + bz * b_bs + (long long)(tile_n + lrow) * ldb + lhalf * 16;
    } else {
        gAf = (const float*)Av + bz * a_bs + (long long)(tile_m + lrow) * lda + lhalf * 16;
        gBf = (const float*)Bv + bz * b_bs + (long long)(tile_n + lrow) * ldb + lhalf * 16;
    }

    float acc[2][8][4];
#pragma unroll
    for (int i = 0; i < 2; i++)
#pragma unroll
        for (int j = 0; j < 8; j++)
#pragma unroll
            for (int t = 0; t < 4; t++) acc[i][j][t] = 0.0f;

    // Prefetch registers
    float4 ra[4], rb[4];     // !IN16 path
    uint4  ha[2], hb[2];     // IN16 path

    if (IN16) {
        ha[0] = *reinterpret_cast<const uint4*>(gAh + 0);
        ha[1] = *reinterpret_cast<const uint4*>(gAh + 8);
        hb[0] = *reinterpret_cast<const uint4*>(gBh + 0);
        hb[1] = *reinterpret_cast<const uint4*>(gBh + 8);
    } else {
#pragma unroll
        for (int i = 0; i < 4; i++) {
            ra[i] = *reinterpret_cast<const float4*>(gAf + i * 4);
            rb[i] = *reinterpret_cast<const float4*>(gBf + i * 4);
        }
    }

    const int nchunks = K / BK;
    for (int c = 0; c < nchunks; c++) {
        const uint32_t stoff = (c & 1) * STAGE_BYTES;
        char* stp = smem + stoff;

        // Stage current chunk into swizzled SMEM (fp16)
        if (IN16) {
            *reinterpret_cast<uint4*>(stp + sts_o0)         = ha[0];
            *reinterpret_cast<uint4*>(stp + sts_o1)         = ha[1];
            *reinterpret_cast<uint4*>(stp + PLANE + sts_o0) = hb[0];
            *reinterpret_cast<uint4*>(stp + PLANE + sts_o1) = hb[1];
        } else {
            uint4 u0, u1;
            u0.x = pack_h2(ra[0].x, ra[0].y); u0.y = pack_h2(ra[0].z, ra[0].w);
            u0.z = pack_h2(ra[1].x, ra[1].y); u0.w = pack_h2(ra[1].z, ra[1].w);
            u1.x = pack_h2(ra[2].x, ra[2].y); u1.y = pack_h2(ra[2].z, ra[2].w);
            u1.z = pack_h2(ra[3].x, ra[3].y); u1.w = pack_h2(ra[3].z, ra[3].w);
            *reinterpret_cast<uint4*>(stp + sts_o0) = u0;
            *reinterpret_cast<uint4*>(stp + sts_o1) = u1;
            u0.x = pack_h2(rb[0].x, rb[0].y); u0.y = pack_h2(rb[0].z, rb[0].w);
            u0.z = pack_h2(rb[1].x, rb[1].y); u0.w = pack_h2(rb[1].z, rb[1].w);
            u1.x = pack_h2(rb[2].x, rb[2].y); u1.y = pack_h2(rb[2].z, rb[2].w);
            u1.z = pack_h2(rb[3].x, rb[3].y); u1.w = pack_h2(rb[3].z, rb[3].w);
            *reinterpret_cast<uint4*>(stp + PLANE + sts_o0) = u0;
            *reinterpret_cast<uint4*>(stp + PLANE + sts_o1) = u1;
        }
        __syncthreads();

        // Prefetch next chunk while computing this one
        if (c + 1 < nchunks) {
            if (IN16) {
                const __half* pA = gAh + (long long)(c + 1) * BK;
                const __half* pB = gBh + (long long)(c + 1) * BK;
                ha[0] = *reinterpret_cast<const uint4*>(pA + 0);
                ha[1] = *reinterpret_cast<const uint4*>(pA + 8);
                hb[0] = *reinterpret_cast<const uint4*>(pB + 0);
                hb[1] = *reinterpret_cast<const uint4*>(pB + 8);
            } else {
                const float* pA = gAf + (long long)(c + 1) * BK;
                const float* pB = gBf + (long long)(c + 1) * BK;
#pragma unroll
                for (int i = 0; i < 4; i++) {
                    ra[i] = *reinterpret_cast<const float4*>(pA + i * 4);
                    rb[i] = *reinterpret_cast<const float4*>(pB + i * 4);
                }
            }
        }

        // MMA over the staged chunk
        const uint32_t sA = sbase + stoff;
        const uint32_t sB = sbase + stoff + PLANE;
        const int lr = lane & 15;           // ldmatrix row within 16
        const int lg = lane >> 4;           // k granule 0/1

#pragma unroll
        for (int ks = 0; ks < 2; ks++) {
            const uint32_t g = ks * 2 + lg;

            uint32_t afr[2][4];
#pragma unroll
            for (int mt = 0; mt < 2; mt++) {
                const int row = wm * 32 + mt * 16 + lr;
                const uint32_t off = row * 64 + ((g ^ ((row >> 1) & 3)) << 4);
                LDSM_X4(afr[mt][0], afr[mt][1], afr[mt][2], afr[mt][3], sA + off);
            }
            uint32_t bfr[4][4];
#pragma unroll
            for (int bt = 0; bt < 4; bt++) {
                const int row = wn * 64 + bt * 16 + lr;
                const uint32_t off = row * 64 + ((g ^ ((row >> 1) & 3)) << 4);
                LDSM_X4(bfr[bt][0], bfr[bt][1], bfr[bt][2], bfr[bt][3], sB + off);
            }
#pragma unroll
            for (int mt = 0; mt < 2; mt++) {
#pragma unroll
                for (int bt = 0; bt < 4; bt++) {
                    MMA16816F16(acc[mt][bt * 2 + 0], afr[mt], bfr[bt][0], bfr[bt][2]);
                    MMA16816F16(acc[mt][bt * 2 + 1], afr[mt], bfr[bt][1], bfr[bt][3]);
                }
            }
        }
        __syncthreads();
    }

    // Epilogue: frag m16n8 -> thread (lane>>2, (lane&3)*2), row halves +8
    const int er = lane >> 2;
    const int ec = (lane & 3) * 2;
#pragma unroll
    for (int mt = 0; mt < 2; mt++) {
#pragma unroll
        for (int half = 0; half < 2; half++) {
            const long long grow = tile_m + wm * 32 + mt * 16 + half * 8 + er;
#pragma unroll
            for (int nt = 0; nt < 8; nt++) {
                const int gcol = tile_n + wn * 64 + nt * 8 + ec;
                float ox = alpha * acc[mt][nt][half * 2 + 0];
                float oy = alpha * acc[mt][nt][half * 2 + 1];
                if (bias != nullptr) {
                    ox += __ldg(bias + gcol + 0);
                    oy += __ldg(bias + gcol + 1);
                }
                if (OUT16) {
                    __half* C = (__half*)Cv + bz * c_bs;
                    *reinterpret_cast<__half2*>(C + grow * ldc + gcol) =
                        __floats2half2_rn(ox, oy);
                } else {
                    float* C = (float*)Cv + bz * c_bs;
                    float2 o; o.x = ox; o.y = oy;
                    *reinterpret_cast<float2*>(C + grow * ldc + gcol) = o;
                }
            }
        }
    }
}

// ---------------------------------------------------------------------------
// v [B][S][E] -> vT [B][E][S]  (fp16, 32x32 smem tiles)
// ---------------------------------------------------------------------------
__global__ void __launch_bounds__(1024)
transpose16_kernel(const __half* __restrict__ v, __half* __restrict__ vt)
{
    __shared__ __half tile[32][33];
    const int b  = blockIdx.z;
    const int d0 = blockIdx.x * 32;
    const int t0 = blockIdx.y * 32;
    const int tx = threadIdx.x;
    const int ty = threadIdx.y;

    tile[ty][tx] = v[((long long)b * SEQ + t0 + ty) * EMB + d0 + tx];
    __syncthreads();
    vt[((long long)b * EMB + d0 + ty) * SEQ + t0 + tx] = tile[tx][ty];
}

// ---------------------------------------------------------------------------
// Row softmax: read fp32 scores, write fp16 probabilities.
// One 256-thread block per row of length SEQ; 8 contiguous elems per thread.
// ---------------------------------------------------------------------------
__global__ void __launch_bounds__(256)
softmax16_kernel(const float* __restrict__ s, __half* __restrict__ p)
{
    const float* row = s + (long long)blockIdx.x * SEQ;
    __half* prow     = p + (long long)blockIdx.x * SEQ;
    const int tid = threadIdx.x;
    __shared__ float red[256];

    float4 v0 = *reinterpret_cast<const float4*>(row + tid * 8);
    float4 v1 = *reinterpret_cast<const float4*>(row + tid * 8 + 4);
    float r[8] = {v0.x, v0.y, v0.z, v0.w, v1.x, v1.y, v1.z, v1.w};

    float m = -3.402823466e+38f;
#pragma unroll
    for (int i = 0; i < 8; i++) m = fmaxf(m, r[i]);
    red[tid] = m;
    __syncthreads();
#pragma unroll
    for (int stp = 128; stp > 0; stp >>= 1) {
        if (tid < stp) red[tid] = fmaxf(red[tid], red[tid + stp]);
        __syncthreads();
    }
    m = red[0];
    __syncthreads();

    float sum = 0.0f;
#pragma unroll
    for (int i = 0; i < 8; i++) {
        r[i] = __expf(r[i] - m);
        sum += r[i];
    }
    red[tid] = sum;
    __syncthreads();
#pragma unroll
    for (int stp = 128; stp > 0; stp >>= 1) {
        if (tid < stp) red[tid] += red[tid + stp];
        __syncthreads();
    }
    const float inv = 1.0f / red[0];

#pragma unroll
    for (int i = 0; i < 4; i++) {
        *reinterpret_cast<__half2*>(prow + tid * 8 + i * 2) =
            __floats2half2_rn(r[i * 2] * inv, r[i * 2 + 1] * inv);
    }
}

// ---------------------------------------------------------------------------
// kernel_launch
// ---------------------------------------------------------------------------
extern "C" void kernel_launch(void* const* d_in, const int* in_sizes, int n_in,
                              void* d_out, int out_size)
{
    const float* x  = (const float*)d_in[0];
    const float* Wq = (const float*)d_in[1];
    const float* bq = (const float*)d_in[2];
    const float* Wk = (const float*)d_in[3];
    const float* bk = (const float*)d_in[4];
    const float* Wv = (const float*)d_in[5];
    const float* bv = (const float*)d_in[6];
    float* out = (float*)d_out;

    __half *q, *k, *v, *vt, *p;
    float  *s;
    cudaGetSymbolAddress((void**)&q,  g_q);
    cudaGetSymbolAddress((void**)&k,  g_k);
    cudaGetSymbolAddress((void**)&v,  g_v);
    cudaGetSymbolAddress((void**)&vt, g_vt);
    cudaGetSymbolAddress((void**)&s,  g_s);
    cudaGetSymbolAddress((void**)&p,  g_p);

    cudaFuncSetAttribute(gemm_h_kernel<false, true>,
                         cudaFuncAttributeMaxDynamicSharedMemorySize, GSMEM);
    cudaFuncSetAttribute(gemm_h_kernel<true, false>,
                         cudaFuncAttributeMaxDynamicSharedMemorySize, GSMEM);

    const float scale = 1.0f / sqrtf((float)EMB);
    const long long SE = (long long)SEQ * EMB;     // 2M
    const long long SS = (long long)SEQ * SEQ;     // 4M

    // 1) QKV projections: fp32 in -> fp16 out, [32768,1024] = x @ W^T + b
    {
        dim3 grid(EMB / BN, MTOT / BM, 1);
        gemm_h_kernel<false, true><<<grid, 256, GSMEM>>>(
            x, Wq, bq, q, EMB, EMB, EMB, EMB, 1.0f, 0, 0, 0);
        gemm_h_kernel<false, true><<<grid, 256, GSMEM>>>(
            x, Wk, bk, k, EMB, EMB, EMB, EMB, 1.0f, 0, 0, 0);
        gemm_h_kernel<false, true><<<grid, 256, GSMEM>>>(
            x, Wv, bv, v, EMB, EMB, EMB, EMB, 1.0f, 0, 0, 0);
    }

    // 2) Transpose v -> vT [B][E][S] (fp16)
    {
        dim3 grid(EMB / 32, SEQ / 32, BATCH);
        transpose16_kernel<<<grid, dim3(32, 32, 1)>>>(v, vt);
    }

    // 3) Scores: per batch, S = scale * q @ k^T  (fp16 in, fp32 out)
    {
        dim3 grid(SEQ / BN, SEQ / BM, BATCH);
        gemm_h_kernel<true, false><<<grid, 256, GSMEM>>>(
            q, k, nullptr, s, EMB, EMB, EMB, SEQ, scale, SE, SE, SS);
    }

    // 4) Softmax (fp32 -> fp16 P)
    softmax16_kernel<<<BATCH * SEQ, 256>>>(s, p);

    // 5) Output: per batch, O[s,d] = sum_t P[s,t] * vT[d,t]  (fp16 in, fp32 out)
    {
        dim3 grid(EMB / BN, SEQ / BM, BATCH);
        gemm_h_kernel<true, false><<<grid, 256, GSMEM>>>(
            p, vt, nullptr, out, SEQ, SEQ, SEQ, EMB, 1.0f, SS, SE, SE);
    }
}

// round 5
// speedup vs baseline: 6.7069x; 1.8069x over previous
#include <cuda_runtime.h>
#include <cuda_fp16.h>
#include <cstdint>
#include <math.h>

// ---------------------------------------------------------------------------
// Problem constants
// ---------------------------------------------------------------------------
#define BATCH 16
#define SEQ   2048
#define EMB   1024
#define MTOT  (BATCH * SEQ)          // 32768

// ---------------------------------------------------------------------------
// Scratch (__device__ globals; no allocation allowed)
// ---------------------------------------------------------------------------
__device__ __half g_xh[(size_t)MTOT * EMB];
__device__ __half g_wq[(size_t)EMB * EMB];
__device__ __half g_wk[(size_t)EMB * EMB];
__device__ __half g_wv[(size_t)EMB * EMB];
__device__ __half g_q[(size_t)MTOT * EMB];
__device__ __half g_k[(size_t)MTOT * EMB];
__device__ __half g_v[(size_t)MTOT * EMB];
__device__ __half g_vt[(size_t)MTOT * EMB];           // [B][E][S]
__device__ float  g_s[(size_t)BATCH * SEQ * SEQ];
__device__ __half g_p[(size_t)BATCH * SEQ * SEQ];

// ---------------------------------------------------------------------------
// Helpers (plain sm_80+ ISA: compiles under compute_103 target)
// ---------------------------------------------------------------------------
__device__ __forceinline__ uint32_t smem_u32(const void* p) {
    uint32_t a;
    asm("{ .reg .u64 t; cvta.to.shared.u64 t, %1; cvt.u32.u64 %0, t; }"
        : "=r"(a) : "l"(p));
    return a;
}

#define LDSM_X4(r0, r1, r2, r3, addr)                                        \
    asm volatile("ldmatrix.sync.aligned.m8n8.x4.shared.b16 "                 \
                 "{%0,%1,%2,%3}, [%4];"                                      \
                 : "=r"(r0), "=r"(r1), "=r"(r2), "=r"(r3) : "r"(addr))

#define MMA16816F16(d, a, b0, b1)                                            \
    asm volatile("mma.sync.aligned.m16n8k16.row.col.f32.f16.f16.f32 "        \
                 "{%0,%1,%2,%3},{%4,%5,%6,%7},{%8,%9},{%0,%1,%2,%3};"        \
                 : "+f"((d)[0]), "+f"((d)[1]), "+f"((d)[2]), "+f"((d)[3])    \
                 : "r"((a)[0]), "r"((a)[1]), "r"((a)[2]), "r"((a)[3]),       \
                   "r"(b0), "r"(b1))

#define CP_ASYNC16(dst_u32, src_ptr)                                         \
    asm volatile("cp.async.cg.shared.global [%0], [%1], 16;"                 \
                 :: "r"(dst_u32), "l"(src_ptr))
#define CP_COMMIT() asm volatile("cp.async.commit_group;" ::: "memory")
#define CP_WAIT2()  asm volatile("cp.async.wait_group 2;" ::: "memory")

// ---------------------------------------------------------------------------
// fp16 NT GEMM (mma.sync, fp32 accumulate), cp.async 4-stage pipeline:
//   C[m,n] = alpha * sum_k A[m,k] * B[n,k]  (+ bias[n])
// A,B __half in global. OUT16 selects fp16 vs fp32 output.
// CTA tile 128x128x32, 8 warps (4m x 2n), swizzled SMEM, 1 sync per chunk.
// ---------------------------------------------------------------------------
#define BM 128
#define BN 128
#define BK 32
#define STAGES 4
#define PLANE 8192                        // 128 rows x 64 B (BK fp16)
#define STAGE_BYTES (2 * PLANE)           // A, B
#define GSMEM (STAGES * STAGE_BYTES)      // 64 KB

template <bool OUT16>
__global__ void __launch_bounds__(256)
gemm_h_kernel(const __half* __restrict__ A,
              const __half* __restrict__ B,
              const float* __restrict__ bias,
              void* __restrict__ Cv,
              int K, int lda, int ldb, int ldc, float alpha,
              long long a_bs, long long b_bs, long long c_bs)
{
    extern __shared__ char smem[];
    const uint32_t sbase = smem_u32(smem);

    const int tid  = threadIdx.x;
    const int wid  = tid >> 5;
    const int lane = tid & 31;

    const long long bz = blockIdx.z;
    const int tile_m = blockIdx.y * BM;
    const int tile_n = blockIdx.x * BN;

    // warp tile: 4 warps in m (32 rows each), 2 in n (64 cols each)
    const int wm = wid & 3;
    const int wn = wid >> 2;

    // Loader mapping: thread -> (row 0..127, half 0/1 of 16 fp16 elements)
    const int lrow  = tid >> 1;
    const int lhalf = tid & 1;
    const uint32_t swz    = (lrow >> 1) & 3;
    const uint32_t sts_o0 = lrow * 64 + (((lhalf * 2 + 0) ^ swz) << 4);
    const uint32_t sts_o1 = lrow * 64 + (((lhalf * 2 + 1) ^ swz) << 4);

    const __half* gA = A + bz * a_bs + (long long)(tile_m + lrow) * lda + lhalf * 16;
    const __half* gB = B + bz * b_bs + (long long)(tile_n + lrow) * ldb + lhalf * 16;

    float acc[2][8][4];
#pragma unroll
    for (int i = 0; i < 2; i++)
#pragma unroll
        for (int j = 0; j < 8; j++)
#pragma unroll
            for (int t = 0; t < 4; t++) acc[i][j][t] = 0.0f;

    const int nchunks = K / BK;

    // Prologue: issue STAGES-1 stages
#pragma unroll
    for (int s = 0; s < STAGES - 1; s++) {
        const uint32_t st = sbase + s * STAGE_BYTES;
        const __half* pA = gA + (long long)s * BK;
        const __half* pB = gB + (long long)s * BK;
        CP_ASYNC16(st + sts_o0,         pA);
        CP_ASYNC16(st + sts_o1,         pA + 8);
        CP_ASYNC16(st + PLANE + sts_o0, pB);
        CP_ASYNC16(st + PLANE + sts_o1, pB + 8);
        CP_COMMIT();
    }

    const int lr = lane & 15;           // ldmatrix row within 16
    const int lg = lane >> 4;           // k granule 0/1

    for (int c = 0; c < nchunks; c++) {
        CP_WAIT2();                     // stage c resident (STAGES-2 pending ok)
        __syncthreads();

        const uint32_t st = sbase + (c % STAGES) * STAGE_BYTES;
        const uint32_t sA = st;
        const uint32_t sB = st + PLANE;

#pragma unroll
        for (int ks = 0; ks < 2; ks++) {
            const uint32_t g = ks * 2 + lg;

            uint32_t afr[2][4];
#pragma unroll
            for (int mt = 0; mt < 2; mt++) {
                const int row = wm * 32 + mt * 16 + lr;
                const uint32_t off = row * 64 + ((g ^ ((row >> 1) & 3)) << 4);
                LDSM_X4(afr[mt][0], afr[mt][1], afr[mt][2], afr[mt][3], sA + off);
            }
            uint32_t bfr[4][4];
#pragma unroll
            for (int bt = 0; bt < 4; bt++) {
                const int row = wn * 64 + bt * 16 + lr;
                const uint32_t off = row * 64 + ((g ^ ((row >> 1) & 3)) << 4);
                LDSM_X4(bfr[bt][0], bfr[bt][1], bfr[bt][2], bfr[bt][3], sB + off);
            }
#pragma unroll
            for (int mt = 0; mt < 2; mt++) {
#pragma unroll
                for (int bt = 0; bt < 4; bt++) {
                    MMA16816F16(acc[mt][bt * 2 + 0], afr[mt], bfr[bt][0], bfr[bt][2]);
                    MMA16816F16(acc[mt][bt * 2 + 1], afr[mt], bfr[bt][1], bfr[bt][3]);
                }
            }
        }

        // Issue the next stage (buffer freed by the sync above)
        const int ns = c + STAGES - 1;
        if (ns < nchunks) {
            const uint32_t nst = sbase + (ns % STAGES) * STAGE_BYTES;
            const __half* pA = gA + (long long)ns * BK;
            const __half* pB = gB + (long long)ns * BK;
            CP_ASYNC16(nst + sts_o0,         pA);
            CP_ASYNC16(nst + sts_o1,         pA + 8);
            CP_ASYNC16(nst + PLANE + sts_o0, pB);
            CP_ASYNC16(nst + PLANE + sts_o1, pB + 8);
        }
        CP_COMMIT();
    }

    // Epilogue: frag m16n8 -> thread (lane>>2, (lane&3)*2), row halves +8
    const int er = lane >> 2;
    const int ec = (lane & 3) * 2;
#pragma unroll
    for (int mt = 0; mt < 2; mt++) {
#pragma unroll
        for (int half = 0; half < 2; half++) {
            const long long grow = tile_m + wm * 32 + mt * 16 + half * 8 + er;
#pragma unroll
            for (int nt = 0; nt < 8; nt++) {
                const int gcol = tile_n + wn * 64 + nt * 8 + ec;
                float ox = alpha * acc[mt][nt][half * 2 + 0];
                float oy = alpha * acc[mt][nt][half * 2 + 1];
                if (bias != nullptr) {
                    ox += __ldg(bias + gcol + 0);
                    oy += __ldg(bias + gcol + 1);
                }
                if (OUT16) {
                    __half* C = (__half*)Cv + bz * c_bs;
                    *reinterpret_cast<__half2*>(C + grow * ldc + gcol) =
                        __floats2half2_rn(ox, oy);
                } else {
                    float* C = (float*)Cv + bz * c_bs;
                    float2 o; o.x = ox; o.y = oy;
                    *reinterpret_cast<float2*>(C + grow * ldc + gcol) = o;
                }
            }
        }
    }
}

// ---------------------------------------------------------------------------
// fp32 -> fp16 convert, 8 elements/thread
// ---------------------------------------------------------------------------
__global__ void __launch_bounds__(256)
convert16_kernel(const float* __restrict__ in, __half* __restrict__ out)
{
    const long long i = ((long long)blockIdx.x * 256 + threadIdx.x) * 8;
    const float4 a = *reinterpret_cast<const float4*>(in + i);
    const float4 b = *reinterpret_cast<const float4*>(in + i + 4);
    uint4 u;
    __half2 t;
    t = __floats2half2_rn(a.x, a.y); u.x = *reinterpret_cast<uint32_t*>(&t);
    t = __floats2half2_rn(a.z, a.w); u.y = *reinterpret_cast<uint32_t*>(&t);
    t = __floats2half2_rn(b.x, b.y); u.z = *reinterpret_cast<uint32_t*>(&t);
    t = __floats2half2_rn(b.z, b.w); u.w = *reinterpret_cast<uint32_t*>(&t);
    *reinterpret_cast<uint4*>(out + i) = u;
}

// ---------------------------------------------------------------------------
// v [B][S][E] -> vT [B][E][S]  (fp16, 32x32 smem tiles)
// ---------------------------------------------------------------------------
__global__ void __launch_bounds__(1024)
transpose16_kernel(const __half* __restrict__ v, __half* __restrict__ vt)
{
    __shared__ __half tile[32][33];
    const int b  = blockIdx.z;
    const int d0 = blockIdx.x * 32;
    const int t0 = blockIdx.y * 32;
    const int tx = threadIdx.x;
    const int ty = threadIdx.y;

    tile[ty][tx] = v[((long long)b * SEQ + t0 + ty) * EMB + d0 + tx];
    __syncthreads();
    vt[((long long)b * EMB + d0 + ty) * SEQ + t0 + tx] = tile[tx][ty];
}

// ---------------------------------------------------------------------------
// Row softmax: read fp32 scores, write fp16 probabilities.
// ---------------------------------------------------------------------------
__global__ void __launch_bounds__(256)
softmax16_kernel(const float* __restrict__ s, __half* __restrict__ p)
{
    const float* row = s + (long long)blockIdx.x * SEQ;
    __half* prow     = p + (long long)blockIdx.x * SEQ;
    const int tid = threadIdx.x;
    __shared__ float red[256];

    float4 v0 = *reinterpret_cast<const float4*>(row + tid * 8);
    float4 v1 = *reinterpret_cast<const float4*>(row + tid * 8 + 4);
    float r[8] = {v0.x, v0.y, v0.z, v0.w, v1.x, v1.y, v1.z, v1.w};

    float m = -3.402823466e+38f;
#pragma unroll
    for (int i = 0; i < 8; i++) m = fmaxf(m, r[i]);
    red[tid] = m;
    __syncthreads();
#pragma unroll
    for (int stp = 128; stp > 0; stp >>= 1) {
        if (tid < stp) red[tid] = fmaxf(red[tid], red[tid + stp]);
        __syncthreads();
    }
    m = red[0];
    __syncthreads();

    float sum = 0.0f;
#pragma unroll
    for (int i = 0; i < 8; i++) {
        r[i] = __expf(r[i] - m);
        sum += r[i];
    }
    red[tid] = sum;
    __syncthreads();
#pragma unroll
    for (int stp = 128; stp > 0; stp >>= 1) {
        if (tid < stp) red[tid] += red[tid + stp];
        __syncthreads();
    }
    const float inv = 1.0f / red[0];

#pragma unroll
    for (int i = 0; i < 4; i++) {
        *reinterpret_cast<__half2*>(prow + tid * 8 + i * 2) =
            __floats2half2_rn(r[i * 2] * inv, r[i * 2 + 1] * inv);
    }
}

// ---------------------------------------------------------------------------
// kernel_launch
// ---------------------------------------------------------------------------
extern "C" void kernel_launch(void* const* d_in, const int* in_sizes, int n_in,
                              void* d_out, int out_size)
{
    const float* x  = (const float*)d_in[0];
    const float* Wq = (const float*)d_in[1];
    const float* bq = (const float*)d_in[2];
    const float* Wk = (const float*)d_in[3];
    const float* bk = (const float*)d_in[4];
    const float* Wv = (const float*)d_in[5];
    const float* bv = (const float*)d_in[6];
    float* out = (float*)d_out;

    __half *xh, *wq, *wk, *wv, *q, *k, *v, *vt, *p;
    float  *s;
    cudaGetSymbolAddress((void**)&xh, g_xh);
    cudaGetSymbolAddress((void**)&wq, g_wq);
    cudaGetSymbolAddress((void**)&wk, g_wk);
    cudaGetSymbolAddress((void**)&wv, g_wv);
    cudaGetSymbolAddress((void**)&q,  g_q);
    cudaGetSymbolAddress((void**)&k,  g_k);
    cudaGetSymbolAddress((void**)&v,  g_v);
    cudaGetSymbolAddress((void**)&vt, g_vt);
    cudaGetSymbolAddress((void**)&s,  g_s);
    cudaGetSymbolAddress((void**)&p,  g_p);

    cudaFuncSetAttribute(gemm_h_kernel<true>,
                         cudaFuncAttributeMaxDynamicSharedMemorySize, GSMEM);
    cudaFuncSetAttribute(gemm_h_kernel<false>,
                         cudaFuncAttributeMaxDynamicSharedMemorySize, GSMEM);

    const float scale = 1.0f / sqrtf((float)EMB);
    const long long SE = (long long)SEQ * EMB;     // 2M
    const long long SS = (long long)SEQ * SEQ;     // 4M

    // 0) fp32 -> fp16 conversions
    convert16_kernel<<<(MTOT * (long long)EMB) / 2048, 256>>>(x, xh);
    convert16_kernel<<<(EMB * EMB) / 2048, 256>>>(Wq, wq);
    convert16_kernel<<<(EMB * EMB) / 2048, 256>>>(Wk, wk);
    convert16_kernel<<<(EMB * EMB) / 2048, 256>>>(Wv, wv);

    // 1) QKV projections: fp16 in -> fp16 out, [32768,1024] = x @ W^T + b
    {
        dim3 grid(EMB / BN, MTOT / BM, 1);
        gemm_h_kernel<true><<<grid, 256, GSMEM>>>(
            xh, wq, bq, q, EMB, EMB, EMB, EMB, 1.0f, 0, 0, 0);
        gemm_h_kernel<true><<<grid, 256, GSMEM>>>(
            xh, wk, bk, k, EMB, EMB, EMB, EMB, 1.0f, 0, 0, 0);
        gemm_h_kernel<true><<<grid, 256, GSMEM>>>(
            xh, wv, bv, v, EMB, EMB, EMB, EMB, 1.0f, 0, 0, 0);
    }

    // 2) Transpose v -> vT [B][E][S] (fp16)
    {
        dim3 grid(EMB / 32, SEQ / 32, BATCH);
        transpose16_kernel<<<grid, dim3(32, 32, 1)>>>(v, vt);
    }

    // 3) Scores: per batch, S = scale * q @ k^T  (fp16 in, fp32 out)
    {
        dim3 grid(SEQ / BN, SEQ / BM, BATCH);
        gemm_h_kernel<false><<<grid, 256, GSMEM>>>(
            q, k, nullptr, s, EMB, EMB, EMB, SEQ, scale, SE, SE, SS);
    }

    // 4) Softmax (fp32 -> fp16 P)
    softmax16_kernel<<<BATCH * SEQ, 256>>>(s, p);

    // 5) Output: per batch, O[s,d] = sum_t P[s,t] * vT[d,t]  (fp16 in, fp32 out)
    {
        dim3 grid(EMB / BN, SEQ / BM, BATCH);
        gemm_h_kernel<false><<<grid, 256, GSMEM>>>(
            p, vt, nullptr, out, SEQ, SEQ, SEQ, EMB, 1.0f, SS, SE, SE);
    }
}